// round 12
// baseline (speedup 1.0000x reference)
#include <cuda_runtime.h>
#include <cuda_bf16.h>
#include <cstdint>

// MultiHeadAttention: B=4, S=2048, D_IN=1024, H=16, D_HEAD=64
// Round 12: flash ping-pong — PV trails QK by one iteration; PV(kb-1) MMAs
// manually interleaved with softmax(kb) exp2/pack chunks. 3-stage KV ring,
// 1 CTA/SM (144KB smem, no reg cap). GEMMs unchanged from round 11.

#define BB   4
#define SS   2048
#define DIN  1024
#define HH   16
#define DH   64
#define MROWS (BB * SS)          // 8192
#define XSZ  (MROWS * DIN)
#define SCALE_Q 0.18033688011112042f   // 0.125 * log2(e)

// ---------------- scratch (device globals; no cudaMalloc allowed) -----------
__device__ __nv_bfloat16 g_Xh[3][XSZ];
__device__ __nv_bfloat16 g_Xl[3][XSZ];
__device__ __nv_bfloat16 g_Qh[XSZ];
__device__ __nv_bfloat16 g_Ql[XSZ];
__device__ __nv_bfloat16 g_Kh[XSZ];
__device__ __nv_bfloat16 g_Kl[XSZ];
__device__ __nv_bfloat16 g_Vh[XSZ];
__device__ __nv_bfloat16 g_Vl[XSZ];
__device__ __nv_bfloat16 g_Oh[XSZ];
__device__ __nv_bfloat16 g_Ol[XSZ];
__device__ __nv_bfloat16 g_Wh[4][DIN * DIN];
__device__ __nv_bfloat16 g_Wl[4][DIN * DIN];

// ============================ asm helpers ====================================
__device__ __forceinline__ uint32_t smem_u32(const void* p) {
    return (uint32_t)__cvta_generic_to_shared((void*)p);
}
__device__ __forceinline__ void ldsm4(uint32_t* r, uint32_t addr) {
    asm volatile("ldmatrix.sync.aligned.m8n8.x4.shared.b16 {%0,%1,%2,%3}, [%4];"
                 : "=r"(r[0]), "=r"(r[1]), "=r"(r[2]), "=r"(r[3]) : "r"(addr));
}
__device__ __forceinline__ void ldsm4t(uint32_t* r, uint32_t addr) {
    asm volatile("ldmatrix.sync.aligned.m8n8.x4.trans.shared.b16 {%0,%1,%2,%3}, [%4];"
                 : "=r"(r[0]), "=r"(r[1]), "=r"(r[2]), "=r"(r[3]) : "r"(addr));
}
__device__ __forceinline__ void mma16816(float* d, const uint32_t* a, const uint32_t* b) {
    asm volatile(
        "mma.sync.aligned.m16n8k16.row.col.f32.bf16.bf16.f32 "
        "{%0,%1,%2,%3}, {%4,%5,%6,%7}, {%8,%9}, {%0,%1,%2,%3};"
        : "+f"(d[0]), "+f"(d[1]), "+f"(d[2]), "+f"(d[3])
        : "r"(a[0]), "r"(a[1]), "r"(a[2]), "r"(a[3]), "r"(b[0]), "r"(b[1]));
}
__device__ __forceinline__ void cp16(uint32_t dst, const void* src) {
    asm volatile("cp.async.cg.shared.global [%0], [%1], 16;"
                 :: "r"(dst), "l"(src) : "memory");
}
#define CP_COMMIT() asm volatile("cp.async.commit_group;" ::: "memory")
#define CP_WAIT0()  asm volatile("cp.async.wait_group 0;" ::: "memory")
#define CP_WAIT1()  asm volatile("cp.async.wait_group 1;" ::: "memory")
__device__ __forceinline__ uint32_t packbf(float lo, float hi) {
    __nv_bfloat16 l = __float2bfloat16(lo), h = __float2bfloat16(hi);
    uint16_t lu = *(uint16_t*)&l, hu = *(uint16_t*)&h;
    return (uint32_t)lu | ((uint32_t)hu << 16);
}

// ====================== fp32 -> bf16 split converters ========================
__global__ void split3_kernel(const float4* __restrict__ X0,
                              const float4* __restrict__ X1,
                              const float4* __restrict__ X2) {
    int z = blockIdx.y;
    const float4* X = (z == 0) ? X0 : (z == 1) ? X1 : X2;
    long i = (long)blockIdx.x * 256 + threadIdx.x;
    float4 v = X[i];
    float xs[4] = {v.x, v.y, v.z, v.w};
    __nv_bfloat16 h[4], l[4];
#pragma unroll
    for (int j = 0; j < 4; j++) {
        h[j] = __float2bfloat16(xs[j]);
        l[j] = __float2bfloat16(xs[j] - __bfloat162float(h[j]));
    }
    *(uint2*)(&g_Xh[z][i * 4]) = *(uint2*)h;
    *(uint2*)(&g_Xl[z][i * 4]) = *(uint2*)l;
}

// m=0 (Wq) pre-scaled by SCALE_Q (softmax in exp2 domain).
__global__ void wsplit_kernel(const float* __restrict__ Wq,
                              const float* __restrict__ Wk,
                              const float* __restrict__ Wv,
                              const float* __restrict__ Wo) {
    int m = blockIdx.y;
    int idx = blockIdx.x * 256 + threadIdx.x;   // n*1024 + k
    int k = idx & 1023;
    int n = idx >> 10;
    float x;
    if (m < 3) {
        const float* W = (m == 0) ? Wq : (m == 1) ? Wk : Wv;
        int h = n >> 6, d = n & 63;
        x = W[((long)h * DIN + k) * DH + d];
        if (m == 0) x *= SCALE_Q;
    } else {
        x = Wo[(long)k * DIN + n];
    }
    __nv_bfloat16 hi = __float2bfloat16(x);
    g_Wh[m][idx] = hi;
    g_Wl[m][idx] = __float2bfloat16(x - __bfloat162float(hi));
}

// ============== mma.sync GEMM core (cp.async pipelined) ======================
#define KC    32
#define ASTR  40
#define TILE_UNITS (128 * ASTR)            // 5120 bf16
#define STAGE_UNITS (4 * TILE_UNITS)       // 20480
#define SMEM_GEMM (2 * STAGE_UNITS * 2)    // 81920 bytes

__device__ __forceinline__ void issue_tile4(uint32_t sb, int stage,
                                            const __nv_bfloat16* const* srcs,
                                            int k0, int t) {
#pragma unroll
    for (int i = 0; i < 8; i++) {
        int u = t + 256 * i;
        int w = u >> 9;
        int rem = u & 511;
        int r = rem >> 2;
        int c = rem & 3;
        uint32_t dst = sb + (uint32_t)(stage * STAGE_UNITS + w * TILE_UNITS
                                       + r * ASTR + c * 8) * 2;
        cp16(dst, srcs[w] + k0 + (long)r * DIN + c * 8);
    }
}

__device__ __forceinline__ void gemm_core(
    uint32_t sb, const __nv_bfloat16* const* srcs, float acc[4][4][4],
    int t, int wid, int lane)
{
    const int wm = (wid >> 2) * 64;
    const int wn = (wid & 3) * 32;
    const int a_r  = (lane & 7) + ((lane >> 3) & 1) * 8;
    const int a_kk = (lane >> 4) * 8;
    const int b_n  = (lane & 7) + (lane >> 4) * 8;
    const int b_kk = ((lane >> 3) & 1) * 8;

    issue_tile4(sb, 0, srcs, 0, t);
    CP_COMMIT();

    const int NC = DIN / KC;   // 32
    for (int c = 0; c < NC; c++) {
        const int cur = c & 1;
        CP_WAIT0();
        __syncthreads();
        if (c + 1 < NC) {
            issue_tile4(sb, 1 - cur, srcs, (c + 1) * KC, t);
            CP_COMMIT();
        }

        const uint32_t stage_b = sb + cur * (STAGE_UNITS * 2);
#pragma unroll
        for (int ks = 0; ks < 2; ks++) {
            uint32_t bh[2][4], bl[2][4];
#pragma unroll
            for (int nf2 = 0; nf2 < 2; nf2++) {
                uint32_t off = (uint32_t)((wn + nf2 * 16 + b_n) * ASTR + ks * 16 + b_kk) * 2;
                ldsm4(bh[nf2], stage_b + TILE_UNITS * 4 + off);
                ldsm4(bl[nf2], stage_b + TILE_UNITS * 6 + off);
            }
            uint32_t ah[2][4], al[2][4];
            {
                uint32_t off0 = (uint32_t)((wm + a_r) * ASTR + ks * 16 + a_kk) * 2;
                ldsm4(ah[0], stage_b + off0);
                ldsm4(al[0], stage_b + TILE_UNITS * 2 + off0);
            }
#pragma unroll
            for (int mf = 0; mf < 4; mf++) {
                const int curb = mf & 1;
                if (mf < 3) {
                    uint32_t offn = (uint32_t)((wm + (mf + 1) * 16 + a_r) * ASTR
                                               + ks * 16 + a_kk) * 2;
                    ldsm4(ah[1 - curb], stage_b + offn);
                    ldsm4(al[1 - curb], stage_b + TILE_UNITS * 2 + offn);
                }
#pragma unroll
                for (int nf = 0; nf < 4; nf++) {
                    const uint32_t* bhf = &bh[nf >> 1][(nf & 1) * 2];
                    const uint32_t* blf = &bl[nf >> 1][(nf & 1) * 2];
                    mma16816(acc[mf][nf], ah[curb], bhf);
                    mma16816(acc[mf][nf], ah[curb], blf);
                    mma16816(acc[mf][nf], al[curb], bhf);
                }
            }
        }
    }
}

__global__ __launch_bounds__(256, 2) void gemm_qkv(
    const float* __restrict__ bq, const float* __restrict__ bk,
    const float* __restrict__ bv)
{
    extern __shared__ __nv_bfloat16 smem[];
    const uint32_t sb = smem_u32(smem);
    const int t = threadIdx.x, wid = t >> 5, lane = t & 31;
    const int m0 = blockIdx.y * 128, n0 = blockIdx.x * 128;
    const int z = blockIdx.z;

    const float* bias = (z == 0) ? bq : (z == 1) ? bk : bv;
    __nv_bfloat16* Ch = (z == 0) ? g_Qh : (z == 1) ? g_Kh : g_Vh;
    __nv_bfloat16* Cl = (z == 0) ? g_Ql : (z == 1) ? g_Kl : g_Vl;
    const float bscale = (z == 0) ? SCALE_Q : 1.0f;

    const __nv_bfloat16* srcs[4] = {
        &g_Xh[z][(long)m0 * DIN], &g_Xl[z][(long)m0 * DIN],
        &g_Wh[z][(long)n0 * DIN], &g_Wl[z][(long)n0 * DIN] };

    float acc[4][4][4];
#pragma unroll
    for (int i = 0; i < 4; i++)
#pragma unroll
        for (int j = 0; j < 4; j++)
#pragma unroll
            for (int e = 0; e < 4; e++) acc[i][j][e] = 0.f;

    gemm_core(sb, srcs, acc, t, wid, lane);

    const int wm = (wid >> 2) * 64;
    const int wn = (wid & 3) * 32;
    const int em = lane >> 2;
    const int en = (lane & 3) * 2;
#pragma unroll
    for (int mf = 0; mf < 4; mf++) {
#pragma unroll
        for (int half = 0; half < 2; half++) {
            long row = m0 + wm + mf * 16 + em + half * 8;
#pragma unroll
            for (int nf = 0; nf < 4; nf++) {
                int col = n0 + wn + nf * 8 + en;
                float v0 = acc[mf][nf][half * 2 + 0] + bias[col + 0] * bscale;
                float v1 = acc[mf][nf][half * 2 + 1] + bias[col + 1] * bscale;
                __nv_bfloat16 h0 = __float2bfloat16(v0);
                __nv_bfloat16 h1 = __float2bfloat16(v1);
                uint16_t h0u = *(uint16_t*)&h0, h1u = *(uint16_t*)&h1;
                *(uint32_t*)(Ch + row * DIN + col) =
                    (uint32_t)h0u | ((uint32_t)h1u << 16);
                *(uint32_t*)(Cl + row * DIN + col) =
                    packbf(v0 - __bfloat162float(h0), v1 - __bfloat162float(h1));
            }
        }
    }
}

__global__ __launch_bounds__(256, 2) void gemm_out(
    const __nv_bfloat16* __restrict__ Ah, const __nv_bfloat16* __restrict__ Al,
    const __nv_bfloat16* __restrict__ Bh, const __nv_bfloat16* __restrict__ Bl,
    const float* __restrict__ bias, float* __restrict__ C)
{
    extern __shared__ __nv_bfloat16 smem[];
    const uint32_t sb = smem_u32(smem);
    const int t = threadIdx.x, wid = t >> 5, lane = t & 31;
    const int m0 = blockIdx.y * 128, n0 = blockIdx.x * 128;

    const __nv_bfloat16* srcs[4] = {
        Ah + (long)m0 * DIN, Al + (long)m0 * DIN,
        Bh + (long)n0 * DIN, Bl + (long)n0 * DIN };

    float acc[4][4][4];
#pragma unroll
    for (int i = 0; i < 4; i++)
#pragma unroll
        for (int j = 0; j < 4; j++)
#pragma unroll
            for (int e = 0; e < 4; e++) acc[i][j][e] = 0.f;

    gemm_core(sb, srcs, acc, t, wid, lane);

    const int wm = (wid >> 2) * 64;
    const int wn = (wid & 3) * 32;
    const int em = lane >> 2;
    const int en = (lane & 3) * 2;
#pragma unroll
    for (int mf = 0; mf < 4; mf++) {
#pragma unroll
        for (int half = 0; half < 2; half++) {
            long row = m0 + wm + mf * 16 + em + half * 8;
#pragma unroll
            for (int nf = 0; nf < 4; nf++) {
                int col = n0 + wn + nf * 8 + en;
                float2 v;
                v.x = acc[mf][nf][half * 2 + 0] + bias[col + 0];
                v.y = acc[mf][nf][half * 2 + 1] + bias[col + 1];
                *(float2*)(C + row * DIN + col) = v;
            }
        }
    }
}

// ============ flash attention: ping-pong (PV trails QK), 3-stage KV ring =====
#define AST 72
#define FA_Q_UNITS (128 * AST)             // 9216 units
#define FA_KV_TILE (64 * AST)              // 4608 units
#define FA_STAGE_UNITS (4 * FA_KV_TILE)    // 18432 units (Kh,Kl,Vh,Vl)
#define STG_BYTES (FA_STAGE_UNITS * 2)     // 36864 bytes
#define SMEM_FA ((2 * FA_Q_UNITS + 3 * FA_STAGE_UNITS) * 2)   // 147456 bytes

__device__ __forceinline__ void issue_kv(uint32_t dbase,
                                         const __nv_bfloat16* const* gkv,
                                         long off, int t) {
#pragma unroll
    for (int i = 0; i < 8; i++) {
        int u = t + 256 * i;            // 0..2047
        int w = u >> 9;
        int rem = u & 511;
        int r = rem >> 3;               // 0..63
        int c = rem & 7;                // 8 x 16B = full 128B row
        uint32_t dst = dbase + (uint32_t)(w * FA_KV_TILE + r * AST + c * 8) * 2;
        cp16(dst, gkv[w] + off + (long)r * DIN + c * 8);
    }
}

__global__ __launch_bounds__(256, 1) void flash_mma_kernel() {
    extern __shared__ __nv_bfloat16 sm[];
    const uint32_t sb = smem_u32(sm);
    const int t = threadIdx.x, warp = t >> 5, lane = t & 31;
    const int b = blockIdx.z, h = blockIdx.y;
    const int q0 = blockIdx.x * 128;

    __nv_bfloat16* sQh = sm;
    __nv_bfloat16* sQl = sm + FA_Q_UNITS;
    const uint32_t bQh = sb;
    const uint32_t bQl = sb + FA_Q_UNITS * 2;
    const uint32_t bKV = sb + 2 * FA_Q_UNITS * 2;   // 3-stage ring base

    const int a_r  = (lane & 7) + ((lane >> 3) & 1) * 8;
    const int a_kk = (lane >> 4) * 8;
    const int b_n  = (lane & 7) + (lane >> 4) * 8;
    const int b_kk = ((lane >> 3) & 1) * 8;
    const int v_kv = (lane & 7) + ((lane >> 3) & 1) * 8;
    const int v_d  = (lane >> 4) * 8;

    const long kvbase0 = (long)(b * SS) * DIN + h * DH;
    const __nv_bfloat16* gkv[4];
    gkv[0] = g_Kh + kvbase0; gkv[1] = g_Kl + kvbase0;
    gkv[2] = g_Vh + kvbase0; gkv[3] = g_Vl + kvbase0;

    // fill stage 0
    issue_kv(bKV, gkv, 0, t);
    CP_COMMIT();

    // load Q tile (plain; visible after first __syncthreads)
    {
        long base = (long)(b * SS + q0) * DIN + h * DH;
#pragma unroll
        for (int i = 0; i < 4; i++) {
            int u = t + 256 * i;
            int r = u >> 3, c = u & 7;
            *(uint4*)(sQh + r * AST + c * 8) = *(const uint4*)(g_Qh + base + (long)r * DIN + c * 8);
            *(uint4*)(sQl + r * AST + c * 8) = *(const uint4*)(g_Ql + base + (long)r * DIN + c * 8);
        }
    }

    float oacc[8][4];
#pragma unroll
    for (int i = 0; i < 8; i++)
#pragma unroll
        for (int j = 0; j < 4; j++) oacc[i][j] = 0.f;
    float m0 = -1e30f, m1 = -1e30f, sl0 = 0.f, sl1 = 0.f;
    float alc0 = 0.f, alc1 = 0.f;          // alpha carry for next iteration
    uint32_t php[4][4], plp[4][4];          // P fragments of previous chunk

    const int NKB = SS / 64;               // 32

    // ---------------- prologue: kb = 0 (QK + softmax + pack, no PV) ----------
    {
        issue_kv(bKV + STG_BYTES, gkv, (long)64 * DIN, t);   // fill stage 1
        CP_COMMIT();
        CP_WAIT1();            // stage 0 landed (stage-1 fill may be in flight)
        __syncthreads();

        float sacc[8][4];
#pragma unroll
        for (int i = 0; i < 8; i++)
#pragma unroll
            for (int j = 0; j < 4; j++) sacc[i][j] = 0.f;
#pragma unroll
        for (int ks = 0; ks < 4; ks++) {
            uint32_t ah[4], al[4];
            uint32_t qoff = (uint32_t)((warp * 16 + a_r) * AST + ks * 16 + a_kk) * 2;
            ldsm4(ah, bQh + qoff);
            ldsm4(al, bQl + qoff);
#pragma unroll
            for (int g = 0; g < 4; g++) {
                uint32_t kh4[4], kl4[4];
                uint32_t koff = (uint32_t)((g * 16 + b_n) * AST + ks * 16 + b_kk) * 2;
                ldsm4(kh4, bKV + koff);
                ldsm4(kl4, bKV + FA_KV_TILE * 2 + koff);
                mma16816(sacc[g * 2],     ah, kh4);
                mma16816(sacc[g * 2],     ah, kl4);
                mma16816(sacc[g * 2],     al, kh4);
                mma16816(sacc[g * 2 + 1], ah, kh4 + 2);
                mma16816(sacc[g * 2 + 1], ah, kl4 + 2);
                mma16816(sacc[g * 2 + 1], al, kh4 + 2);
            }
        }
        float mx0 = -1e30f, mx1 = -1e30f;
#pragma unroll
        for (int nf = 0; nf < 8; nf++) {
            mx0 = fmaxf(mx0, fmaxf(sacc[nf][0], sacc[nf][1]));
            mx1 = fmaxf(mx1, fmaxf(sacc[nf][2], sacc[nf][3]));
        }
        mx0 = fmaxf(mx0, __shfl_xor_sync(0xffffffffu, mx0, 1));
        mx0 = fmaxf(mx0, __shfl_xor_sync(0xffffffffu, mx0, 2));
        mx1 = fmaxf(mx1, __shfl_xor_sync(0xffffffffu, mx1, 1));
        mx1 = fmaxf(mx1, __shfl_xor_sync(0xffffffffu, mx1, 2));
        m0 = mx0;  m1 = mx1;
        alc0 = 0.f; alc1 = 0.f;            // oacc is zero; scale value irrelevant
        float rs0 = 0.f, rs1 = 0.f;
#pragma unroll
        for (int ks = 0; ks < 4; ks++) {
#pragma unroll
            for (int q = 0; q < 2; q++) {
                int nf = 2 * ks + q;
                float p0 = exp2f(sacc[nf][0] - m0);
                float p1 = exp2f(sacc[nf][1] - m0);
                float p2 = exp2f(sacc[nf][2] - m1);
                float p3 = exp2f(sacc[nf][3] - m1);
                rs0 += p0 + p1;  rs1 += p2 + p3;
                __nv_bfloat16 c0 = __float2bfloat16(p0), c1 = __float2bfloat16(p1);
                __nv_bfloat16 c2 = __float2bfloat16(p2), c3 = __float2bfloat16(p3);
                uint16_t u0 = *(uint16_t*)&c0, u1 = *(uint16_t*)&c1;
                uint16_t u2 = *(uint16_t*)&c2, u3 = *(uint16_t*)&c3;
                php[ks][q * 2 + 0] = (uint32_t)u0 | ((uint32_t)u1 << 16);
                php[ks][q * 2 + 1] = (uint32_t)u2 | ((uint32_t)u3 << 16);
                plp[ks][q * 2 + 0] = packbf(p0 - __bfloat162float(c0),
                                            p1 - __bfloat162float(c1));
                plp[ks][q * 2 + 1] = packbf(p2 - __bfloat162float(c2),
                                            p3 - __bfloat162float(c3));
            }
        }
        rs0 += __shfl_xor_sync(0xffffffffu, rs0, 1);
        rs0 += __shfl_xor_sync(0xffffffffu, rs0, 2);
        rs1 += __shfl_xor_sync(0xffffffffu, rs1, 1);
        rs1 += __shfl_xor_sync(0xffffffffu, rs1, 2);
        sl0 = rs0;  sl1 = rs1;
    }

    // ---------------- main loop: kb = 1 .. NKB-1 -----------------------------
    for (int kb = 1; kb < NKB; kb++) {
        const uint32_t bufK = bKV + (uint32_t)((kb % 3) * STG_BYTES);
        const uint32_t bufV = bKV + (uint32_t)(((kb - 1) % 3) * STG_BYTES);

        __syncthreads();   // all warps done with stage kb-2 (PV reads last iter)
        if (kb + 1 < NKB) {
            issue_kv(bKV + (uint32_t)(((kb + 1) % 3) * STG_BYTES),
                     gkv, (long)(kb + 1) * 64 * DIN, t);
            CP_COMMIT();
            CP_WAIT1();    // stage kb landed; stage kb+1 may be in flight
        } else {
            CP_WAIT0();
        }
        __syncthreads();   // stage kb visible to all warps

        // ---- QK(kb)
        float sacc[8][4];
#pragma unroll
        for (int i = 0; i < 8; i++)
#pragma unroll
            for (int j = 0; j < 4; j++) sacc[i][j] = 0.f;
#pragma unroll
        for (int ks = 0; ks < 4; ks++) {
            uint32_t ah[4], al[4];
            uint32_t qoff = (uint32_t)((warp * 16 + a_r) * AST + ks * 16 + a_kk) * 2;
            ldsm4(ah, bQh + qoff);
            ldsm4(al, bQl + qoff);
#pragma unroll
            for (int g = 0; g < 4; g++) {
                uint32_t kh4[4], kl4[4];
                uint32_t koff = (uint32_t)((g * 16 + b_n) * AST + ks * 16 + b_kk) * 2;
                ldsm4(kh4, bufK + koff);
                ldsm4(kl4, bufK + FA_KV_TILE * 2 + koff);
                mma16816(sacc[g * 2],     ah, kh4);
                mma16816(sacc[g * 2],     ah, kl4);
                mma16816(sacc[g * 2],     al, kh4);
                mma16816(sacc[g * 2 + 1], ah, kh4 + 2);
                mma16816(sacc[g * 2 + 1], ah, kl4 + 2);
                mma16816(sacc[g * 2 + 1], al, kh4 + 2);
            }
        }

        // ---- scale oacc by carried alpha (must precede PV(kb-1) MMAs)
#pragma unroll
        for (int gd = 0; gd < 8; gd++) {
            oacc[gd][0] *= alc0;  oacc[gd][1] *= alc0;
            oacc[gd][2] *= alc1;  oacc[gd][3] *= alc1;
        }

        // ---- row max for chunk kb
        float mx0 = -1e30f, mx1 = -1e30f;
#pragma unroll
        for (int nf = 0; nf < 8; nf++) {
            mx0 = fmaxf(mx0, fmaxf(sacc[nf][0], sacc[nf][1]));
            mx1 = fmaxf(mx1, fmaxf(sacc[nf][2], sacc[nf][3]));
        }
        mx0 = fmaxf(mx0, __shfl_xor_sync(0xffffffffu, mx0, 1));
        mx0 = fmaxf(mx0, __shfl_xor_sync(0xffffffffu, mx0, 2));
        mx1 = fmaxf(mx1, __shfl_xor_sync(0xffffffffu, mx1, 1));
        mx1 = fmaxf(mx1, __shfl_xor_sync(0xffffffffu, mx1, 2));
        float nm0 = fmaxf(m0, mx0), nm1 = fmaxf(m1, mx1);
        float an0 = exp2f(m0 - nm0), an1 = exp2f(m1 - nm1);
        m0 = nm0;  m1 = nm1;

        // ---- interleaved: PV(kb-1) MMA blocks + softmax(kb) exp2/pack chunks
        uint32_t phn[4][4], pln[4][4];
        float rs0 = 0.f, rs1 = 0.f;
#pragma unroll
        for (int ks = 0; ks < 4; ks++) {
            // PV(kb-1) block ks (independent of softmax below)
#pragma unroll
            for (int g = 0; g < 4; g++) {
                uint32_t vh4[4], vl4[4];
                uint32_t voff = (uint32_t)((ks * 16 + v_kv) * AST + g * 16 + v_d) * 2;
                ldsm4t(vh4, bufV + FA_KV_TILE * 4 + voff);
                ldsm4t(vl4, bufV + FA_KV_TILE * 6 + voff);
                mma16816(oacc[g * 2],     php[ks], vh4);
                mma16816(oacc[g * 2],     php[ks], vl4);
                mma16816(oacc[g * 2],     plp[ks], vh4);
                mma16816(oacc[g * 2 + 1], php[ks], vh4 + 2);
                mma16816(oacc[g * 2 + 1], php[ks], vl4 + 2);
                mma16816(oacc[g * 2 + 1], plp[ks], vh4 + 2);
            }
            // softmax chunk for nf = 2ks, 2ks+1 (overlaps MMA latency)
#pragma unroll
            for (int q = 0; q < 2; q++) {
                int nf = 2 * ks + q;
                float p0 = exp2f(sacc[nf][0] - m0);
                float p1 = exp2f(sacc[nf][1] - m0);
                float p2 = exp2f(sacc[nf][2] - m1);
                float p3 = exp2f(sacc[nf][3] - m1);
                rs0 += p0 + p1;  rs1 += p2 + p3;
                __nv_bfloat16 c0 = __float2bfloat16(p0), c1 = __float2bfloat16(p1);
                __nv_bfloat16 c2 = __float2bfloat16(p2), c3 = __float2bfloat16(p3);
                uint16_t u0 = *(uint16_t*)&c0, u1 = *(uint16_t*)&c1;
                uint16_t u2 = *(uint16_t*)&c2, u3 = *(uint16_t*)&c3;
                phn[ks][q * 2 + 0] = (uint32_t)u0 | ((uint32_t)u1 << 16);
                phn[ks][q * 2 + 1] = (uint32_t)u2 | ((uint32_t)u3 << 16);
                pln[ks][q * 2 + 0] = packbf(p0 - __bfloat162float(c0),
                                            p1 - __bfloat162float(c1));
                pln[ks][q * 2 + 1] = packbf(p2 - __bfloat162float(c2),
                                            p3 - __bfloat162float(c3));
            }
        }
        rs0 += __shfl_xor_sync(0xffffffffu, rs0, 1);
        rs0 += __shfl_xor_sync(0xffffffffu, rs0, 2);
        rs1 += __shfl_xor_sync(0xffffffffu, rs1, 1);
        rs1 += __shfl_xor_sync(0xffffffffu, rs1, 2);
        sl0 = sl0 * an0 + rs0;
        sl1 = sl1 * an1 + rs1;
        alc0 = an0;  alc1 = an1;

        // rotate P fragments
#pragma unroll
        for (int ks = 0; ks < 4; ks++)
#pragma unroll
            for (int e = 0; e < 4; e++) {
                php[ks][e] = phn[ks][e];
                plp[ks][e] = pln[ks][e];
            }
    }

    // ---------------- epilogue: trailing PV(NKB-1) ---------------------------
    {
        const uint32_t bufV = bKV + (uint32_t)(((NKB - 1) % 3) * STG_BYTES);
#pragma unroll
        for (int gd = 0; gd < 8; gd++) {
            oacc[gd][0] *= alc0;  oacc[gd][1] *= alc0;
            oacc[gd][2] *= alc1;  oacc[gd][3] *= alc1;
        }
#pragma unroll
        for (int ks = 0; ks < 4; ks++) {
#pragma unroll
            for (int g = 0; g < 4; g++) {
                uint32_t vh4[4], vl4[4];
                uint32_t voff = (uint32_t)((ks * 16 + v_kv) * AST + g * 16 + v_d) * 2;
                ldsm4t(vh4, bufV + FA_KV_TILE * 4 + voff);
                ldsm4t(vl4, bufV + FA_KV_TILE * 6 + voff);
                mma16816(oacc[g * 2],     php[ks], vh4);
                mma16816(oacc[g * 2],     php[ks], vl4);
                mma16816(oacc[g * 2],     plp[ks], vh4);
                mma16816(oacc[g * 2 + 1], php[ks], vh4 + 2);
                mma16816(oacc[g * 2 + 1], php[ks], vl4 + 2);
                mma16816(oacc[g * 2 + 1], plp[ks], vh4 + 2);
            }
        }
    }

    // ---- normalize, split, write [row][h*64+d]
    float inv0 = 1.f / sl0, inv1 = 1.f / sl1;
    long row0 = (long)(b * SS + q0 + warp * 16 + (lane >> 2));
    int colb = h * DH + (lane & 3) * 2;
#pragma unroll
    for (int gd = 0; gd < 8; gd++) {
        int col = colb + gd * 8;
        {
            float v0 = oacc[gd][0] * inv0, v1 = oacc[gd][1] * inv0;
            __nv_bfloat16 h0 = __float2bfloat16(v0), h1 = __float2bfloat16(v1);
            uint16_t h0u = *(uint16_t*)&h0, h1u = *(uint16_t*)&h1;
            *(uint32_t*)(g_Oh + row0 * DIN + col) = (uint32_t)h0u | ((uint32_t)h1u << 16);
            *(uint32_t*)(g_Ol + row0 * DIN + col) =
                packbf(v0 - __bfloat162float(h0), v1 - __bfloat162float(h1));
        }
        {
            float v0 = oacc[gd][2] * inv1, v1 = oacc[gd][3] * inv1;
            __nv_bfloat16 h0 = __float2bfloat16(v0), h1 = __float2bfloat16(v1);
            uint16_t h0u = *(uint16_t*)&h0, h1u = *(uint16_t*)&h1;
            *(uint32_t*)(g_Oh + (row0 + 8) * DIN + col) = (uint32_t)h0u | ((uint32_t)h1u << 16);
            *(uint32_t*)(g_Ol + (row0 + 8) * DIN + col) =
                packbf(v0 - __bfloat162float(h0), v1 - __bfloat162float(h1));
        }
    }
}

// ---------------- launcher ---------------------------------------------------
extern "C" void kernel_launch(void* const* d_in, const int* in_sizes, int n_in,
                              void* d_out, int out_size) {
    const float* query = (const float*)d_in[0];
    const float* key_  = (const float*)d_in[1];
    const float* value = (const float*)d_in[2];
    const float* Wq = (const float*)d_in[3];
    const float* bq = (const float*)d_in[4];
    const float* Wk = (const float*)d_in[5];
    const float* bk = (const float*)d_in[6];
    const float* Wv = (const float*)d_in[7];
    const float* bv = (const float*)d_in[8];
    const float* Wo = (const float*)d_in[9];
    const float* bo = (const float*)d_in[10];
    float* out = (float*)d_out;

    __nv_bfloat16 *pWh, *pWl, *pOh, *pOl;
    cudaGetSymbolAddress((void**)&pWh, g_Wh);
    cudaGetSymbolAddress((void**)&pWl, g_Wl);
    cudaGetSymbolAddress((void**)&pOh, g_Oh);
    cudaGetSymbolAddress((void**)&pOl, g_Ol);

    cudaFuncSetAttribute(gemm_qkv,
                         cudaFuncAttributeMaxDynamicSharedMemorySize, SMEM_GEMM);
    cudaFuncSetAttribute(gemm_out,
                         cudaFuncAttributeMaxDynamicSharedMemorySize, SMEM_GEMM);
    cudaFuncSetAttribute(flash_mma_kernel,
                         cudaFuncAttributeMaxDynamicSharedMemorySize, SMEM_FA);

    wsplit_kernel<<<dim3(DIN * DIN / 256, 4), 256>>>(Wq, Wk, Wv, Wo);

    const int splitBlocks = XSZ / 4 / 256;
    split3_kernel<<<dim3(splitBlocks, 3), 256>>>(
        (const float4*)query, (const float4*)key_, (const float4*)value);

    gemm_qkv<<<dim3(DIN / 128, MROWS / 128, 3), 256, SMEM_GEMM>>>(bq, bk, bv);

    flash_mma_kernel<<<dim3(SS / 128, HH, BB), 256, SMEM_FA>>>();

    gemm_out<<<dim3(DIN / 128, MROWS / 128), 256, SMEM_GEMM>>>(
        pOh, pOl, pWh + 3 * DIN * DIN, pWl + 3 * DIN * DIN, bo, out);
}

// round 13
// speedup vs baseline: 1.0764x; 1.0764x over previous
#include <cuda_runtime.h>
#include <cuda_bf16.h>
#include <cstdint>

// MultiHeadAttention: B=4, S=2048, D_IN=1024, H=16, D_HEAD=64
// Round 13: flash reverted to round-11 (best) version; split3 pass deleted —
// fp32->bf16 hi/lo split of X fused into gemm_qkv's A-staging (LDG fp32 one
// chunk ahead, convert+STS after compute). gemm_out unchanged.

#define BB   4
#define SS   2048
#define DIN  1024
#define HH   16
#define DH   64
#define MROWS (BB * SS)          // 8192
#define XSZ  (MROWS * DIN)
#define SCALE_Q 0.18033688011112042f   // 0.125 * log2(e)

// ---------------- scratch (device globals; no cudaMalloc allowed) -----------
__device__ __nv_bfloat16 g_Qh[XSZ];
__device__ __nv_bfloat16 g_Ql[XSZ];
__device__ __nv_bfloat16 g_Kh[XSZ];
__device__ __nv_bfloat16 g_Kl[XSZ];
__device__ __nv_bfloat16 g_Vh[XSZ];
__device__ __nv_bfloat16 g_Vl[XSZ];
__device__ __nv_bfloat16 g_Oh[XSZ];
__device__ __nv_bfloat16 g_Ol[XSZ];
__device__ __nv_bfloat16 g_Wh[4][DIN * DIN];
__device__ __nv_bfloat16 g_Wl[4][DIN * DIN];

// ============================ asm helpers ====================================
__device__ __forceinline__ uint32_t smem_u32(const void* p) {
    return (uint32_t)__cvta_generic_to_shared((void*)p);
}
__device__ __forceinline__ void ldsm4(uint32_t* r, uint32_t addr) {
    asm volatile("ldmatrix.sync.aligned.m8n8.x4.shared.b16 {%0,%1,%2,%3}, [%4];"
                 : "=r"(r[0]), "=r"(r[1]), "=r"(r[2]), "=r"(r[3]) : "r"(addr));
}
__device__ __forceinline__ void ldsm4t(uint32_t* r, uint32_t addr) {
    asm volatile("ldmatrix.sync.aligned.m8n8.x4.trans.shared.b16 {%0,%1,%2,%3}, [%4];"
                 : "=r"(r[0]), "=r"(r[1]), "=r"(r[2]), "=r"(r[3]) : "r"(addr));
}
__device__ __forceinline__ void mma16816(float* d, const uint32_t* a, const uint32_t* b) {
    asm volatile(
        "mma.sync.aligned.m16n8k16.row.col.f32.bf16.bf16.f32 "
        "{%0,%1,%2,%3}, {%4,%5,%6,%7}, {%8,%9}, {%0,%1,%2,%3};"
        : "+f"(d[0]), "+f"(d[1]), "+f"(d[2]), "+f"(d[3])
        : "r"(a[0]), "r"(a[1]), "r"(a[2]), "r"(a[3]), "r"(b[0]), "r"(b[1]));
}
__device__ __forceinline__ void cp16(uint32_t dst, const void* src) {
    asm volatile("cp.async.cg.shared.global [%0], [%1], 16;"
                 :: "r"(dst), "l"(src) : "memory");
}
#define CP_COMMIT() asm volatile("cp.async.commit_group;" ::: "memory")
#define CP_WAIT0()  asm volatile("cp.async.wait_group 0;" ::: "memory")
__device__ __forceinline__ uint32_t packbf(float lo, float hi) {
    __nv_bfloat16 l = __float2bfloat16(lo), h = __float2bfloat16(hi);
    uint16_t lu = *(uint16_t*)&l, hu = *(uint16_t*)&h;
    return (uint32_t)lu | ((uint32_t)hu << 16);
}

// ====================== weight transpose + bf16 split ========================
__global__ void wsplit_kernel(const float* __restrict__ Wq,
                              const float* __restrict__ Wk,
                              const float* __restrict__ Wv,
                              const float* __restrict__ Wo) {
    int m = blockIdx.y;
    int idx = blockIdx.x * 256 + threadIdx.x;   // n*1024 + k
    int k = idx & 1023;
    int n = idx >> 10;
    float x;
    if (m < 3) {
        const float* W = (m == 0) ? Wq : (m == 1) ? Wk : Wv;
        int h = n >> 6, d = n & 63;
        x = W[((long)h * DIN + k) * DH + d];
        if (m == 0) x *= SCALE_Q;
    } else {
        x = Wo[(long)k * DIN + n];
    }
    __nv_bfloat16 hi = __float2bfloat16(x);
    g_Wh[m][idx] = hi;
    g_Wl[m][idx] = __float2bfloat16(x - __bfloat162float(hi));
}

// ============== GEMM common ==================================================
#define KC    32
#define ASTR  40
#define TILE_UNITS (128 * ASTR)            // 5120 bf16
#define STAGE_UNITS (4 * TILE_UNITS)       // 20480
#define SMEM_GEMM (2 * STAGE_UNITS * 2)    // 81920 bytes

__device__ __forceinline__ void issue_tile4(uint32_t sb, int stage,
                                            const __nv_bfloat16* const* srcs,
                                            int k0, int t) {
#pragma unroll
    for (int i = 0; i < 8; i++) {
        int u = t + 256 * i;
        int w = u >> 9;
        int rem = u & 511;
        int r = rem >> 2;
        int c = rem & 3;
        uint32_t dst = sb + (uint32_t)(stage * STAGE_UNITS + w * TILE_UNITS
                                       + r * ASTR + c * 8) * 2;
        cp16(dst, srcs[w] + k0 + (long)r * DIN + c * 8);
    }
}

__device__ __forceinline__ void issue_tileB(uint32_t sb, int stage,
                                            const __nv_bfloat16* Bh,
                                            const __nv_bfloat16* Bl,
                                            int k0, int t) {
#pragma unroll
    for (int i = 0; i < 4; i++) {
        int u = t + 256 * i;            // 0..1023: 2 tiles x 128 rows x 4 chunks
        int w = u >> 9;
        int rem = u & 511;
        int r = rem >> 2;
        int c = rem & 3;
        const __nv_bfloat16* src = (w == 0) ? Bh : Bl;
        uint32_t dst = sb + (uint32_t)(stage * STAGE_UNITS + (2 + w) * TILE_UNITS
                                       + r * ASTR + c * 8) * 2;
        cp16(dst, src + k0 + (long)r * DIN + c * 8);
    }
}

__device__ __forceinline__ void ldgA(const float* __restrict__ X,
                                     int k0, int t, float4 a[4]) {
#pragma unroll
    for (int i = 0; i < 4; i++) {
        int u = t + 256 * i;            // 0..1023: 128 rows x 8 float4
        int r = u >> 3;
        int c4 = u & 7;
        a[i] = *(const float4*)(X + (long)r * DIN + k0 + c4 * 4);
    }
}

__device__ __forceinline__ void cvt_sts_A(__nv_bfloat16* smem, int stage,
                                          const float4 a[4], int t) {
#pragma unroll
    for (int i = 0; i < 4; i++) {
        int u = t + 256 * i;
        int r = u >> 3, c4 = u & 7;
        float xs[4] = {a[i].x, a[i].y, a[i].z, a[i].w};
        __nv_bfloat16 h[4], l[4];
#pragma unroll
        for (int j = 0; j < 4; j++) {
            h[j] = __float2bfloat16(xs[j]);
            l[j] = __float2bfloat16(xs[j] - __bfloat162float(h[j]));
        }
        *(uint2*)(smem + stage * STAGE_UNITS + r * ASTR + c4 * 4) = *(uint2*)h;
        *(uint2*)(smem + stage * STAGE_UNITS + TILE_UNITS + r * ASTR + c4 * 4) = *(uint2*)l;
    }
}

__device__ __forceinline__ void mma_stage(
    uint32_t stage_b, float acc[4][4][4],
    int wm, int wn, int a_r, int a_kk, int b_n, int b_kk)
{
#pragma unroll
    for (int ks = 0; ks < 2; ks++) {
        uint32_t bh[2][4], bl[2][4];
#pragma unroll
        for (int nf2 = 0; nf2 < 2; nf2++) {
            uint32_t off = (uint32_t)((wn + nf2 * 16 + b_n) * ASTR + ks * 16 + b_kk) * 2;
            ldsm4(bh[nf2], stage_b + TILE_UNITS * 4 + off);
            ldsm4(bl[nf2], stage_b + TILE_UNITS * 6 + off);
        }
        uint32_t ah[2][4], al[2][4];
        {
            uint32_t off0 = (uint32_t)((wm + a_r) * ASTR + ks * 16 + a_kk) * 2;
            ldsm4(ah[0], stage_b + off0);
            ldsm4(al[0], stage_b + TILE_UNITS * 2 + off0);
        }
#pragma unroll
        for (int mf = 0; mf < 4; mf++) {
            const int curb = mf & 1;
            if (mf < 3) {
                uint32_t offn = (uint32_t)((wm + (mf + 1) * 16 + a_r) * ASTR
                                           + ks * 16 + a_kk) * 2;
                ldsm4(ah[1 - curb], stage_b + offn);
                ldsm4(al[1 - curb], stage_b + TILE_UNITS * 2 + offn);
            }
#pragma unroll
            for (int nf = 0; nf < 4; nf++) {
                const uint32_t* bhf = &bh[nf >> 1][(nf & 1) * 2];
                const uint32_t* blf = &bl[nf >> 1][(nf & 1) * 2];
                mma16816(acc[mf][nf], ah[curb], bhf);
                mma16816(acc[mf][nf], ah[curb], blf);
                mma16816(acc[mf][nf], al[curb], bhf);
            }
        }
    }
}

// Batched QKV projection with fused fp32->split A staging. grid (8, 64, 3).
__global__ __launch_bounds__(256) void gemm_qkv(
    const float* __restrict__ Xq, const float* __restrict__ Xk,
    const float* __restrict__ Xv,
    const float* __restrict__ bq, const float* __restrict__ bk,
    const float* __restrict__ bv)
{
    extern __shared__ __nv_bfloat16 smem[];
    const uint32_t sb = smem_u32(smem);
    const int t = threadIdx.x, wid = t >> 5, lane = t & 31;
    const int m0 = blockIdx.y * 128, n0 = blockIdx.x * 128;
    const int z = blockIdx.z;

    const float* X    = ((z == 0) ? Xq : (z == 1) ? Xk : Xv) + (long)m0 * DIN;
    const float* bias = (z == 0) ? bq : (z == 1) ? bk : bv;
    __nv_bfloat16* Ch = (z == 0) ? g_Qh : (z == 1) ? g_Kh : g_Vh;
    __nv_bfloat16* Cl = (z == 0) ? g_Ql : (z == 1) ? g_Kl : g_Vl;
    const float bscale = (z == 0) ? SCALE_Q : 1.0f;

    const __nv_bfloat16* Bh = &g_Wh[z][(long)n0 * DIN];
    const __nv_bfloat16* Bl = &g_Wl[z][(long)n0 * DIN];

    const int wm = (wid >> 2) * 64;
    const int wn = (wid & 3) * 32;
    const int a_r  = (lane & 7) + ((lane >> 3) & 1) * 8;
    const int a_kk = (lane >> 4) * 8;
    const int b_n  = (lane & 7) + (lane >> 4) * 8;
    const int b_kk = ((lane >> 3) & 1) * 8;

    float acc[4][4][4];
#pragma unroll
    for (int i = 0; i < 4; i++)
#pragma unroll
        for (int j = 0; j < 4; j++)
#pragma unroll
            for (int e = 0; e < 4; e++) acc[i][j][e] = 0.f;

    issue_tileB(sb, 0, Bh, Bl, 0, t);
    CP_COMMIT();
    {
        float4 a0[4];
        ldgA(X, 0, t, a0);
        cvt_sts_A(smem, 0, a0, t);
    }

    const int NC = DIN / KC;   // 32
    float4 areg[4];
    for (int c = 0; c < NC; c++) {
        const int cur = c & 1;
        const int nxt = 1 - cur;
        CP_WAIT0();
        __syncthreads();              // stage cur (B async + A STS) visible
        if (c + 1 < NC) {
            ldgA(X, (c + 1) * KC, t, areg);   // long-latency LDG hidden by MMAs
            issue_tileB(sb, nxt, Bh, Bl, (c + 1) * KC, t);
            CP_COMMIT();
        }

        mma_stage(sb + cur * (STAGE_UNITS * 2), acc, wm, wn, a_r, a_kk, b_n, b_kk);

        if (c + 1 < NC)
            cvt_sts_A(smem, nxt, areg, t);    // stage nxt free since top-of-loop sync
    }

    const int em = lane >> 2;
    const int en = (lane & 3) * 2;
#pragma unroll
    for (int mf = 0; mf < 4; mf++) {
#pragma unroll
        for (int half = 0; half < 2; half++) {
            long row = m0 + wm + mf * 16 + em + half * 8;
#pragma unroll
            for (int nf = 0; nf < 4; nf++) {
                int col = n0 + wn + nf * 8 + en;
                float v0 = acc[mf][nf][half * 2 + 0] + bias[col + 0] * bscale;
                float v1 = acc[mf][nf][half * 2 + 1] + bias[col + 1] * bscale;
                __nv_bfloat16 h0 = __float2bfloat16(v0);
                __nv_bfloat16 h1 = __float2bfloat16(v1);
                uint16_t h0u = *(uint16_t*)&h0, h1u = *(uint16_t*)&h1;
                *(uint32_t*)(Ch + row * DIN + col) =
                    (uint32_t)h0u | ((uint32_t)h1u << 16);
                *(uint32_t*)(Cl + row * DIN + col) =
                    packbf(v0 - __bfloat162float(h0), v1 - __bfloat162float(h1));
            }
        }
    }
}

// Output projection: A already split (Oh/Ol), all-cp.async staging.
__global__ __launch_bounds__(256, 2) void gemm_out(
    const __nv_bfloat16* __restrict__ Ah, const __nv_bfloat16* __restrict__ Al,
    const __nv_bfloat16* __restrict__ Bh, const __nv_bfloat16* __restrict__ Bl,
    const float* __restrict__ bias, float* __restrict__ C)
{
    extern __shared__ __nv_bfloat16 smem[];
    const uint32_t sb = smem_u32(smem);
    const int t = threadIdx.x, wid = t >> 5, lane = t & 31;
    const int m0 = blockIdx.y * 128, n0 = blockIdx.x * 128;

    const __nv_bfloat16* srcs[4] = {
        Ah + (long)m0 * DIN, Al + (long)m0 * DIN,
        Bh + (long)n0 * DIN, Bl + (long)n0 * DIN };

    const int wm = (wid >> 2) * 64;
    const int wn = (wid & 3) * 32;
    const int a_r  = (lane & 7) + ((lane >> 3) & 1) * 8;
    const int a_kk = (lane >> 4) * 8;
    const int b_n  = (lane & 7) + (lane >> 4) * 8;
    const int b_kk = ((lane >> 3) & 1) * 8;

    float acc[4][4][4];
#pragma unroll
    for (int i = 0; i < 4; i++)
#pragma unroll
        for (int j = 0; j < 4; j++)
#pragma unroll
            for (int e = 0; e < 4; e++) acc[i][j][e] = 0.f;

    issue_tile4(sb, 0, srcs, 0, t);
    CP_COMMIT();

    const int NC = DIN / KC;
    for (int c = 0; c < NC; c++) {
        const int cur = c & 1;
        CP_WAIT0();
        __syncthreads();
        if (c + 1 < NC) {
            issue_tile4(sb, 1 - cur, srcs, (c + 1) * KC, t);
            CP_COMMIT();
        }
        mma_stage(sb + cur * (STAGE_UNITS * 2), acc, wm, wn, a_r, a_kk, b_n, b_kk);
    }

    const int em = lane >> 2;
    const int en = (lane & 3) * 2;
#pragma unroll
    for (int mf = 0; mf < 4; mf++) {
#pragma unroll
        for (int half = 0; half < 2; half++) {
            long row = m0 + wm + mf * 16 + em + half * 8;
#pragma unroll
            for (int nf = 0; nf < 4; nf++) {
                int col = n0 + wn + nf * 8 + en;
                float2 v;
                v.x = acc[mf][nf][half * 2 + 0] + bias[col + 0];
                v.y = acc[mf][nf][half * 2 + 1] + bias[col + 1];
                *(float2*)(C + row * DIN + col) = v;
            }
        }
    }
}

// ============ flash attention (round-11 version: 2-stage KV, 2 CTA/SM) =======
#define AST 72
#define FA_Q_UNITS (128 * AST)             // 9216
#define FA_KV_TILE (64 * AST)              // 4608
#define FA_STAGE_UNITS (4 * FA_KV_TILE)    // 18432
#define SMEM_FA ((2 * FA_Q_UNITS + 2 * FA_STAGE_UNITS) * 2)   // 110592 bytes

__device__ __forceinline__ void issue_kv(uint32_t dbase,
                                         const __nv_bfloat16* const* gkv,
                                         long off, int t) {
#pragma unroll
    for (int i = 0; i < 8; i++) {
        int u = t + 256 * i;            // 0..2047
        int w = u >> 9;
        int rem = u & 511;
        int r = rem >> 3;               // 0..63
        int c = rem & 7;                // 8 x 16B = full 128B row
        uint32_t dst = dbase + (uint32_t)(w * FA_KV_TILE + r * AST + c * 8) * 2;
        cp16(dst, gkv[w] + off + (long)r * DIN + c * 8);
    }
}

__global__ __launch_bounds__(256, 2) void flash_mma_kernel() {
    extern __shared__ __nv_bfloat16 sm[];
    const uint32_t sb = smem_u32(sm);
    const int t = threadIdx.x, warp = t >> 5, lane = t & 31;
    const int b = blockIdx.z, h = blockIdx.y;
    const int q0 = blockIdx.x * 128;

    __nv_bfloat16* sQh = sm;
    __nv_bfloat16* sQl = sm + FA_Q_UNITS;
    const uint32_t bQh = sb;
    const uint32_t bQl = sb + FA_Q_UNITS * 2;
    const uint32_t bKV = sb + 2 * FA_Q_UNITS * 2;

    const int a_r  = (lane & 7) + ((lane >> 3) & 1) * 8;
    const int a_kk = (lane >> 4) * 8;
    const int b_n  = (lane & 7) + (lane >> 4) * 8;
    const int b_kk = ((lane >> 3) & 1) * 8;
    const int v_kv = (lane & 7) + ((lane >> 3) & 1) * 8;
    const int v_d  = (lane >> 4) * 8;

    const long kvbase0 = (long)(b * SS) * DIN + h * DH;
    const __nv_bfloat16* gkv[4];
    gkv[0] = g_Kh + kvbase0; gkv[1] = g_Kl + kvbase0;
    gkv[2] = g_Vh + kvbase0; gkv[3] = g_Vl + kvbase0;

    issue_kv(bKV, gkv, 0, t);
    CP_COMMIT();

    {
        long base = (long)(b * SS + q0) * DIN + h * DH;
#pragma unroll
        for (int i = 0; i < 4; i++) {
            int u = t + 256 * i;
            int r = u >> 3, c = u & 7;
            *(uint4*)(sQh + r * AST + c * 8) = *(const uint4*)(g_Qh + base + (long)r * DIN + c * 8);
            *(uint4*)(sQl + r * AST + c * 8) = *(const uint4*)(g_Ql + base + (long)r * DIN + c * 8);
        }
    }

    float oacc[8][4];
#pragma unroll
    for (int i = 0; i < 8; i++)
#pragma unroll
        for (int j = 0; j < 4; j++) oacc[i][j] = 0.f;
    float m0 = -1e30f, m1 = -1e30f, sl0 = 0.f, sl1 = 0.f;

    const int NKB = SS / 64;
    for (int kb = 0; kb < NKB; kb++) {
        const int cur = kb & 1;
        CP_WAIT0();
        __syncthreads();
        if (kb + 1 < NKB) {
            issue_kv(bKV + (uint32_t)((1 - cur) * FA_STAGE_UNITS) * 2,
                     gkv, (long)(kb + 1) * 64 * DIN, t);
            CP_COMMIT();
        }

        const uint32_t bKh = bKV + (uint32_t)(cur * FA_STAGE_UNITS) * 2;
        const uint32_t bKl = bKh + FA_KV_TILE * 2;
        const uint32_t bVh = bKl + FA_KV_TILE * 2;
        const uint32_t bVl = bVh + FA_KV_TILE * 2;

        float sacc[8][4];
#pragma unroll
        for (int i = 0; i < 8; i++)
#pragma unroll
            for (int j = 0; j < 4; j++) sacc[i][j] = 0.f;

#pragma unroll
        for (int ks = 0; ks < 4; ks++) {
            uint32_t ah[4], al[4];
            uint32_t qoff = (uint32_t)((warp * 16 + a_r) * AST + ks * 16 + a_kk) * 2;
            ldsm4(ah, bQh + qoff);
            ldsm4(al, bQl + qoff);
#pragma unroll
            for (int g = 0; g < 4; g++) {
                uint32_t kh4[4], kl4[4];
                uint32_t koff = (uint32_t)((g * 16 + b_n) * AST + ks * 16 + b_kk) * 2;
                ldsm4(kh4, bKh + koff);
                ldsm4(kl4, bKl + koff);
                mma16816(sacc[g * 2],     ah, kh4);
                mma16816(sacc[g * 2],     ah, kl4);
                mma16816(sacc[g * 2],     al, kh4);
                mma16816(sacc[g * 2 + 1], ah, kh4 + 2);
                mma16816(sacc[g * 2 + 1], ah, kl4 + 2);
                mma16816(sacc[g * 2 + 1], al, kh4 + 2);
            }
        }

        float mx0 = -1e30f, mx1 = -1e30f;
#pragma unroll
        for (int nf = 0; nf < 8; nf++) {
            mx0 = fmaxf(mx0, fmaxf(sacc[nf][0], sacc[nf][1]));
            mx1 = fmaxf(mx1, fmaxf(sacc[nf][2], sacc[nf][3]));
        }
        mx0 = fmaxf(mx0, __shfl_xor_sync(0xffffffffu, mx0, 1));
        mx0 = fmaxf(mx0, __shfl_xor_sync(0xffffffffu, mx0, 2));
        mx1 = fmaxf(mx1, __shfl_xor_sync(0xffffffffu, mx1, 1));
        mx1 = fmaxf(mx1, __shfl_xor_sync(0xffffffffu, mx1, 2));

        float nm0 = fmaxf(m0, mx0), nm1 = fmaxf(m1, mx1);
        float al0 = exp2f(m0 - nm0), al1 = exp2f(m1 - nm1);
        float rs0 = 0.f, rs1 = 0.f;
#pragma unroll
        for (int nf = 0; nf < 8; nf++) {
            sacc[nf][0] = exp2f(sacc[nf][0] - nm0);
            sacc[nf][1] = exp2f(sacc[nf][1] - nm0);
            sacc[nf][2] = exp2f(sacc[nf][2] - nm1);
            sacc[nf][3] = exp2f(sacc[nf][3] - nm1);
            rs0 += sacc[nf][0] + sacc[nf][1];
            rs1 += sacc[nf][2] + sacc[nf][3];
        }
        rs0 += __shfl_xor_sync(0xffffffffu, rs0, 1);
        rs0 += __shfl_xor_sync(0xffffffffu, rs0, 2);
        rs1 += __shfl_xor_sync(0xffffffffu, rs1, 1);
        rs1 += __shfl_xor_sync(0xffffffffu, rs1, 2);
        sl0 = sl0 * al0 + rs0;  m0 = nm0;
        sl1 = sl1 * al1 + rs1;  m1 = nm1;
#pragma unroll
        for (int gd = 0; gd < 8; gd++) {
            oacc[gd][0] *= al0;  oacc[gd][1] *= al0;
            oacc[gd][2] *= al1;  oacc[gd][3] *= al1;
        }

        uint32_t ph[4][4], pl[4][4];
#pragma unroll
        for (int ks = 0; ks < 4; ks++) {
#pragma unroll
            for (int q = 0; q < 2; q++) {
                int nf = 2 * ks + q;
#pragma unroll
                for (int hf = 0; hf < 2; hf++) {
                    float p0 = sacc[nf][hf * 2 + 0];
                    float p1 = sacc[nf][hf * 2 + 1];
                    __nv_bfloat16 b0 = __float2bfloat16(p0);
                    __nv_bfloat16 b1 = __float2bfloat16(p1);
                    uint16_t b0u = *(uint16_t*)&b0, b1u = *(uint16_t*)&b1;
                    ph[ks][q * 2 + hf] = (uint32_t)b0u | ((uint32_t)b1u << 16);
                    pl[ks][q * 2 + hf] = packbf(p0 - __bfloat162float(b0),
                                                p1 - __bfloat162float(b1));
                }
            }
        }

#pragma unroll
        for (int ks = 0; ks < 4; ks++) {
#pragma unroll
            for (int g = 0; g < 4; g++) {
                uint32_t vh4[4], vl4[4];
                uint32_t voff = (uint32_t)((ks * 16 + v_kv) * AST + g * 16 + v_d) * 2;
                ldsm4t(vh4, bVh + voff);
                ldsm4t(vl4, bVl + voff);
                mma16816(oacc[g * 2],     ph[ks], vh4);
                mma16816(oacc[g * 2],     ph[ks], vl4);
                mma16816(oacc[g * 2],     pl[ks], vh4);
                mma16816(oacc[g * 2 + 1], ph[ks], vh4 + 2);
                mma16816(oacc[g * 2 + 1], ph[ks], vl4 + 2);
                mma16816(oacc[g * 2 + 1], pl[ks], vh4 + 2);
            }
        }
    }

    float inv0 = 1.f / sl0, inv1 = 1.f / sl1;
    long row0 = (long)(b * SS + q0 + warp * 16 + (lane >> 2));
    int colb = h * DH + (lane & 3) * 2;
#pragma unroll
    for (int gd = 0; gd < 8; gd++) {
        int col = colb + gd * 8;
        {
            float v0 = oacc[gd][0] * inv0, v1 = oacc[gd][1] * inv0;
            __nv_bfloat16 h0 = __float2bfloat16(v0), h1 = __float2bfloat16(v1);
            uint16_t h0u = *(uint16_t*)&h0, h1u = *(uint16_t*)&h1;
            *(uint32_t*)(g_Oh + row0 * DIN + col) = (uint32_t)h0u | ((uint32_t)h1u << 16);
            *(uint32_t*)(g_Ol + row0 * DIN + col) =
                packbf(v0 - __bfloat162float(h0), v1 - __bfloat162float(h1));
        }
        {
            float v0 = oacc[gd][2] * inv1, v1 = oacc[gd][3] * inv1;
            __nv_bfloat16 h0 = __float2bfloat16(v0), h1 = __float2bfloat16(v1);
            uint16_t h0u = *(uint16_t*)&h0, h1u = *(uint16_t*)&h1;
            *(uint32_t*)(g_Oh + (row0 + 8) * DIN + col) = (uint32_t)h0u | ((uint32_t)h1u << 16);
            *(uint32_t*)(g_Ol + (row0 + 8) * DIN + col) =
                packbf(v0 - __bfloat162float(h0), v1 - __bfloat162float(h1));
        }
    }
}

// ---------------- launcher ---------------------------------------------------
extern "C" void kernel_launch(void* const* d_in, const int* in_sizes, int n_in,
                              void* d_out, int out_size) {
    const float* query = (const float*)d_in[0];
    const float* key_  = (const float*)d_in[1];
    const float* value = (const float*)d_in[2];
    const float* Wq = (const float*)d_in[3];
    const float* bq = (const float*)d_in[4];
    const float* Wk = (const float*)d_in[5];
    const float* bk = (const float*)d_in[6];
    const float* Wv = (const float*)d_in[7];
    const float* bv = (const float*)d_in[8];
    const float* Wo = (const float*)d_in[9];
    const float* bo = (const float*)d_in[10];
    float* out = (float*)d_out;

    __nv_bfloat16 *pWh, *pWl, *pOh, *pOl;
    cudaGetSymbolAddress((void**)&pWh, g_Wh);
    cudaGetSymbolAddress((void**)&pWl, g_Wl);
    cudaGetSymbolAddress((void**)&pOh, g_Oh);
    cudaGetSymbolAddress((void**)&pOl, g_Ol);

    cudaFuncSetAttribute(gemm_qkv,
                         cudaFuncAttributeMaxDynamicSharedMemorySize, SMEM_GEMM);
    cudaFuncSetAttribute(gemm_out,
                         cudaFuncAttributeMaxDynamicSharedMemorySize, SMEM_GEMM);
    cudaFuncSetAttribute(flash_mma_kernel,
                         cudaFuncAttributeMaxDynamicSharedMemorySize, SMEM_FA);

    wsplit_kernel<<<dim3(DIN * DIN / 256, 4), 256>>>(Wq, Wk, Wv, Wo);

    gemm_qkv<<<dim3(DIN / 128, MROWS / 128, 3), 256, SMEM_GEMM>>>(
        query, key_, value, bq, bk, bv);

    flash_mma_kernel<<<dim3(SS / 128, HH, BB), 256, SMEM_FA>>>();

    gemm_out<<<dim3(DIN / 128, MROWS / 128), 256, SMEM_GEMM>>>(
        pOh, pOl, pWh + 3 * DIN * DIN, pWl + 3 * DIN * DIN, bo, out);
}

// round 16
// speedup vs baseline: 1.0784x; 1.0019x over previous
#include <cuda_runtime.h>
#include <cuda_bf16.h>
#include <cstdint>

// MultiHeadAttention: B=4, S=2048, D_IN=1024, H=16, D_HEAD=64
// Round 16: round 15 with the gemm_out A-staging loop geometry FIXED.
// A stage = 2 tiles x 128 rows x 4 uint4 = 1024 uint4 (round 15 ran 2048
// iterations with r up to 255 -> smem overflow corrupted B tiles).

#define BB   4
#define SS   2048
#define DIN  1024
#define HH   16
#define DH   64
#define MROWS (BB * SS)          // 8192
#define XSZ  (MROWS * DIN)
#define SCALE_Q 0.18033688011112042f   // 0.125 * log2(e)

// ---------------- scratch (device globals; no cudaMalloc allowed) -----------
__device__ __nv_bfloat16 g_Qh[XSZ];
__device__ __nv_bfloat16 g_Ql[XSZ];
__device__ __nv_bfloat16 g_Kh[XSZ];
__device__ __nv_bfloat16 g_Kl[XSZ];
__device__ __nv_bfloat16 g_Vh[XSZ];
__device__ __nv_bfloat16 g_Vl[XSZ];
__device__ __nv_bfloat16 g_Oh[XSZ];
__device__ __nv_bfloat16 g_Ol[XSZ];
__device__ __nv_bfloat16 g_Wh[4][DIN * DIN];
__device__ __nv_bfloat16 g_Wl[4][DIN * DIN];

// ============================ asm helpers ====================================
__device__ __forceinline__ uint32_t smem_u32(const void* p) {
    return (uint32_t)__cvta_generic_to_shared((void*)p);
}
__device__ __forceinline__ void ldsm4(uint32_t* r, uint32_t addr) {
    asm volatile("ldmatrix.sync.aligned.m8n8.x4.shared.b16 {%0,%1,%2,%3}, [%4];"
                 : "=r"(r[0]), "=r"(r[1]), "=r"(r[2]), "=r"(r[3]) : "r"(addr));
}
__device__ __forceinline__ void ldsm4t(uint32_t* r, uint32_t addr) {
    asm volatile("ldmatrix.sync.aligned.m8n8.x4.trans.shared.b16 {%0,%1,%2,%3}, [%4];"
                 : "=r"(r[0]), "=r"(r[1]), "=r"(r[2]), "=r"(r[3]) : "r"(addr));
}
__device__ __forceinline__ void mma16816(float* d, const uint32_t* a, const uint32_t* b) {
    asm volatile(
        "mma.sync.aligned.m16n8k16.row.col.f32.bf16.bf16.f32 "
        "{%0,%1,%2,%3}, {%4,%5,%6,%7}, {%8,%9}, {%0,%1,%2,%3};"
        : "+f"(d[0]), "+f"(d[1]), "+f"(d[2]), "+f"(d[3])
        : "r"(a[0]), "r"(a[1]), "r"(a[2]), "r"(a[3]), "r"(b[0]), "r"(b[1]));
}
__device__ __forceinline__ void cp16(uint32_t dst, const void* src) {
    asm volatile("cp.async.cg.shared.global [%0], [%1], 16;"
                 :: "r"(dst), "l"(src) : "memory");
}
#define CP_COMMIT() asm volatile("cp.async.commit_group;" ::: "memory")
#define CP_WAIT0()  asm volatile("cp.async.wait_group 0;" ::: "memory")
__device__ __forceinline__ uint32_t packbf(float lo, float hi) {
    __nv_bfloat16 l = __float2bfloat16(lo), h = __float2bfloat16(hi);
    uint16_t lu = *(uint16_t*)&l, hu = *(uint16_t*)&h;
    return (uint32_t)lu | ((uint32_t)hu << 16);
}

// ====================== weight transpose + bf16 split ========================
__global__ void wsplit_kernel(const float* __restrict__ Wq,
                              const float* __restrict__ Wk,
                              const float* __restrict__ Wv,
                              const float* __restrict__ Wo) {
    int m = blockIdx.y;
    int idx = blockIdx.x * 256 + threadIdx.x;   // n*1024 + k
    int k = idx & 1023;
    int n = idx >> 10;
    float x;
    if (m < 3) {
        const float* W = (m == 0) ? Wq : (m == 1) ? Wk : Wv;
        int h = n >> 6, d = n & 63;
        x = W[((long)h * DIN + k) * DH + d];
        if (m == 0) x *= SCALE_Q;
    } else {
        x = Wo[(long)k * DIN + n];
    }
    __nv_bfloat16 hi = __float2bfloat16(x);
    g_Wh[m][idx] = hi;
    g_Wl[m][idx] = __float2bfloat16(x - __bfloat162float(hi));
}

// ============== GEMM common ==================================================
#define KC    32
#define ASTR  40
#define TILE_UNITS (128 * ASTR)            // 5120 bf16
#define STAGE_UNITS (4 * TILE_UNITS)       // 20480
#define SMEM_GEMM (2 * STAGE_UNITS * 2)    // 81920 bytes

__device__ __forceinline__ void issue_tileB(uint32_t sb, int stage,
                                            const __nv_bfloat16* Bh,
                                            const __nv_bfloat16* Bl,
                                            int k0, int t) {
#pragma unroll
    for (int i = 0; i < 4; i++) {
        int u = t + 256 * i;            // 0..1023: 2 tiles x 128 rows x 4 chunks
        int w = u >> 9;
        int rem = u & 511;
        int r = rem >> 2;
        int c = rem & 3;
        const __nv_bfloat16* src = (w == 0) ? Bh : Bl;
        uint32_t dst = sb + (uint32_t)(stage * STAGE_UNITS + (2 + w) * TILE_UNITS
                                       + r * ASTR + c * 8) * 2;
        cp16(dst, src + k0 + (long)r * DIN + c * 8);
    }
}

// A path (gemm_qkv): LDG fp32 X, convert hi/lo, STS.
__device__ __forceinline__ void ldgA_f32(const float* __restrict__ X,
                                         int k0, int t, float4 a[4]) {
#pragma unroll
    for (int i = 0; i < 4; i++) {
        int u = t + 256 * i;            // 0..1023: 128 rows x 8 float4
        int r = u >> 3;
        int c4 = u & 7;
        a[i] = *(const float4*)(X + (long)r * DIN + k0 + c4 * 4);
    }
}
__device__ __forceinline__ void cvt_sts_A(__nv_bfloat16* smem, int stage,
                                          const float4 a[4], int t) {
#pragma unroll
    for (int i = 0; i < 4; i++) {
        int u = t + 256 * i;
        int r = u >> 3, c4 = u & 7;
        float xs[4] = {a[i].x, a[i].y, a[i].z, a[i].w};
        __nv_bfloat16 h[4], l[4];
#pragma unroll
        for (int j = 0; j < 4; j++) {
            h[j] = __float2bfloat16(xs[j]);
            l[j] = __float2bfloat16(xs[j] - __bfloat162float(h[j]));
        }
        *(uint2*)(smem + stage * STAGE_UNITS + r * ASTR + c4 * 4) = *(uint2*)h;
        *(uint2*)(smem + stage * STAGE_UNITS + TILE_UNITS + r * ASTR + c4 * 4) = *(uint2*)l;
    }
}

// A path (gemm_out): LDG bf16 hi/lo pairs, STS.
// One stage of A = 2 tiles x 128 rows x 4 uint4 = 1024 uint4 (4 iters x 256).
__device__ __forceinline__ void ldgA_bf(const __nv_bfloat16* __restrict__ Ah,
                                        const __nv_bfloat16* __restrict__ Al,
                                        int k0, int t, uint4 a[4]) {
#pragma unroll
    for (int i = 0; i < 4; i++) {
        int u = t + 256 * i;            // 0..1023
        int w = u >> 9;                 // 0: hi tile, 1: lo tile
        int rem = u & 511;
        int r = rem >> 2;               // 0..127
        int c4 = rem & 3;               // 4 x uint4 (8 bf16) per 32-bf16 row
        const __nv_bfloat16* src = (w == 0) ? Ah : Al;
        a[i] = *(const uint4*)(src + (long)r * DIN + k0 + c4 * 8);
    }
}
__device__ __forceinline__ void sts_A_bf(__nv_bfloat16* smem, int stage,
                                         const uint4 a[4], int t) {
#pragma unroll
    for (int i = 0; i < 4; i++) {
        int u = t + 256 * i;
        int w = u >> 9;
        int rem = u & 511;
        int r = rem >> 2;
        int c4 = rem & 3;
        *(uint4*)(smem + stage * STAGE_UNITS + w * TILE_UNITS + r * ASTR + c4 * 8) = a[i];
    }
}

__device__ __forceinline__ void mma_stage(
    uint32_t stage_b, float acc[4][4][4],
    int wm, int wn, int a_r, int a_kk, int b_n, int b_kk)
{
#pragma unroll
    for (int ks = 0; ks < 2; ks++) {
        uint32_t bh[2][4], bl[2][4];
#pragma unroll
        for (int nf2 = 0; nf2 < 2; nf2++) {
            uint32_t off = (uint32_t)((wn + nf2 * 16 + b_n) * ASTR + ks * 16 + b_kk) * 2;
            ldsm4(bh[nf2], stage_b + TILE_UNITS * 4 + off);
            ldsm4(bl[nf2], stage_b + TILE_UNITS * 6 + off);
        }
        uint32_t ah[2][4], al[2][4];
        {
            uint32_t off0 = (uint32_t)((wm + a_r) * ASTR + ks * 16 + a_kk) * 2;
            ldsm4(ah[0], stage_b + off0);
            ldsm4(al[0], stage_b + TILE_UNITS * 2 + off0);
        }
#pragma unroll
        for (int mf = 0; mf < 4; mf++) {
            const int curb = mf & 1;
            if (mf < 3) {
                uint32_t offn = (uint32_t)((wm + (mf + 1) * 16 + a_r) * ASTR
                                           + ks * 16 + a_kk) * 2;
                ldsm4(ah[1 - curb], stage_b + offn);
                ldsm4(al[1 - curb], stage_b + TILE_UNITS * 2 + offn);
            }
#pragma unroll
            for (int nf = 0; nf < 4; nf++) {
                const uint32_t* bhf = &bh[nf >> 1][(nf & 1) * 2];
                const uint32_t* blf = &bl[nf >> 1][(nf & 1) * 2];
                mma16816(acc[mf][nf], ah[curb], bhf);
                mma16816(acc[mf][nf], ah[curb], blf);
                mma16816(acc[mf][nf], al[curb], bhf);
            }
        }
    }
}

// Batched QKV projection with fused fp32->split A staging. grid (8, 64, 3).
__global__ __launch_bounds__(256) void gemm_qkv(
    const float* __restrict__ Xq, const float* __restrict__ Xk,
    const float* __restrict__ Xv,
    const float* __restrict__ bq, const float* __restrict__ bk,
    const float* __restrict__ bv)
{
    extern __shared__ __nv_bfloat16 smem[];
    const uint32_t sb = smem_u32(smem);
    const int t = threadIdx.x, wid = t >> 5, lane = t & 31;
    const int m0 = blockIdx.y * 128, n0 = blockIdx.x * 128;
    const int z = blockIdx.z;

    const float* X    = ((z == 0) ? Xq : (z == 1) ? Xk : Xv) + (long)m0 * DIN;
    const float* bias = (z == 0) ? bq : (z == 1) ? bk : bv;
    __nv_bfloat16* Ch = (z == 0) ? g_Qh : (z == 1) ? g_Kh : g_Vh;
    __nv_bfloat16* Cl = (z == 0) ? g_Ql : (z == 1) ? g_Kl : g_Vl;
    const float bscale = (z == 0) ? SCALE_Q : 1.0f;

    const __nv_bfloat16* Bh = &g_Wh[z][(long)n0 * DIN];
    const __nv_bfloat16* Bl = &g_Wl[z][(long)n0 * DIN];

    const int wm = (wid >> 2) * 64;
    const int wn = (wid & 3) * 32;
    const int a_r  = (lane & 7) + ((lane >> 3) & 1) * 8;
    const int a_kk = (lane >> 4) * 8;
    const int b_n  = (lane & 7) + (lane >> 4) * 8;
    const int b_kk = ((lane >> 3) & 1) * 8;

    float acc[4][4][4];
#pragma unroll
    for (int i = 0; i < 4; i++)
#pragma unroll
        for (int j = 0; j < 4; j++)
#pragma unroll
            for (int e = 0; e < 4; e++) acc[i][j][e] = 0.f;

    issue_tileB(sb, 0, Bh, Bl, 0, t);
    CP_COMMIT();
    {
        float4 a0[4];
        ldgA_f32(X, 0, t, a0);
        cvt_sts_A(smem, 0, a0, t);
    }

    const int NC = DIN / KC;   // 32
    float4 areg[4];
    for (int c = 0; c < NC; c++) {
        const int cur = c & 1;
        const int nxt = 1 - cur;
        CP_WAIT0();
        __syncthreads();
        if (c + 1 < NC) {
            ldgA_f32(X, (c + 1) * KC, t, areg);
            issue_tileB(sb, nxt, Bh, Bl, (c + 1) * KC, t);
            CP_COMMIT();
        }

        mma_stage(sb + cur * (STAGE_UNITS * 2), acc, wm, wn, a_r, a_kk, b_n, b_kk);

        if (c + 1 < NC)
            cvt_sts_A(smem, nxt, areg, t);
    }

    const int em = lane >> 2;
    const int en = (lane & 3) * 2;
#pragma unroll
    for (int mf = 0; mf < 4; mf++) {
#pragma unroll
        for (int half = 0; half < 2; half++) {
            long row = m0 + wm + mf * 16 + em + half * 8;
#pragma unroll
            for (int nf = 0; nf < 4; nf++) {
                int col = n0 + wn + nf * 8 + en;
                float v0 = acc[mf][nf][half * 2 + 0] + bias[col + 0] * bscale;
                float v1 = acc[mf][nf][half * 2 + 1] + bias[col + 1] * bscale;
                __nv_bfloat16 h0 = __float2bfloat16(v0);
                __nv_bfloat16 h1 = __float2bfloat16(v1);
                uint16_t h0u = *(uint16_t*)&h0, h1u = *(uint16_t*)&h1;
                *(uint32_t*)(Ch + row * DIN + col) =
                    (uint32_t)h0u | ((uint32_t)h1u << 16);
                *(uint32_t*)(Cl + row * DIN + col) =
                    packbf(v0 - __bfloat162float(h0), v1 - __bfloat162float(h1));
            }
        }
    }
}

// Output projection: A (Oh/Ol) via LDG+STS (gemm_qkv recipe), B via cp.async.
__global__ __launch_bounds__(256) void gemm_out(
    const __nv_bfloat16* __restrict__ Ah, const __nv_bfloat16* __restrict__ Al,
    const __nv_bfloat16* __restrict__ Bh, const __nv_bfloat16* __restrict__ Bl,
    const float* __restrict__ bias, float* __restrict__ C)
{
    extern __shared__ __nv_bfloat16 smem[];
    const uint32_t sb = smem_u32(smem);
    const int t = threadIdx.x, wid = t >> 5, lane = t & 31;
    const int m0 = blockIdx.y * 128, n0 = blockIdx.x * 128;

    const __nv_bfloat16* Ah0 = Ah + (long)m0 * DIN;
    const __nv_bfloat16* Al0 = Al + (long)m0 * DIN;
    const __nv_bfloat16* Bh0 = Bh + (long)n0 * DIN;
    const __nv_bfloat16* Bl0 = Bl + (long)n0 * DIN;

    const int wm = (wid >> 2) * 64;
    const int wn = (wid & 3) * 32;
    const int a_r  = (lane & 7) + ((lane >> 3) & 1) * 8;
    const int a_kk = (lane >> 4) * 8;
    const int b_n  = (lane & 7) + (lane >> 4) * 8;
    const int b_kk = ((lane >> 3) & 1) * 8;

    float acc[4][4][4];
#pragma unroll
    for (int i = 0; i < 4; i++)
#pragma unroll
        for (int j = 0; j < 4; j++)
#pragma unroll
            for (int e = 0; e < 4; e++) acc[i][j][e] = 0.f;

    issue_tileB(sb, 0, Bh0, Bl0, 0, t);
    CP_COMMIT();
    {
        uint4 a0[4];
        ldgA_bf(Ah0, Al0, 0, t, a0);
        sts_A_bf(smem, 0, a0, t);
    }

    const int NC = DIN / KC;
    uint4 areg[4];
    for (int c = 0; c < NC; c++) {
        const int cur = c & 1;
        const int nxt = 1 - cur;
        CP_WAIT0();
        __syncthreads();
        if (c + 1 < NC) {
            ldgA_bf(Ah0, Al0, (c + 1) * KC, t, areg);
            issue_tileB(sb, nxt, Bh0, Bl0, (c + 1) * KC, t);
            CP_COMMIT();
        }

        mma_stage(sb + cur * (STAGE_UNITS * 2), acc, wm, wn, a_r, a_kk, b_n, b_kk);

        if (c + 1 < NC)
            sts_A_bf(smem, nxt, areg, t);
    }

    const int em = lane >> 2;
    const int en = (lane & 3) * 2;
#pragma unroll
    for (int mf = 0; mf < 4; mf++) {
#pragma unroll
        for (int half = 0; half < 2; half++) {
            long row = m0 + wm + mf * 16 + em + half * 8;
#pragma unroll
            for (int nf = 0; nf < 4; nf++) {
                int col = n0 + wn + nf * 8 + en;
                float2 v;
                v.x = acc[mf][nf][half * 2 + 0] + bias[col + 0];
                v.y = acc[mf][nf][half * 2 + 1] + bias[col + 1];
                *(float2*)(C + row * DIN + col) = v;
            }
        }
    }
}

// ============ flash attention (round-11 version: 2-stage KV, 2 CTA/SM) =======
#define AST 72
#define FA_Q_UNITS (128 * AST)             // 9216
#define FA_KV_TILE (64 * AST)              // 4608
#define FA_STAGE_UNITS (4 * FA_KV_TILE)    // 18432
#define SMEM_FA ((2 * FA_Q_UNITS + 2 * FA_STAGE_UNITS) * 2)   // 110592 bytes

__device__ __forceinline__ void issue_kv(uint32_t dbase,
                                         const __nv_bfloat16* const* gkv,
                                         long off, int t) {
#pragma unroll
    for (int i = 0; i < 8; i++) {
        int u = t + 256 * i;            // 0..2047
        int w = u >> 9;
        int rem = u & 511;
        int r = rem >> 3;               // 0..63
        int c = rem & 7;                // 8 x 16B = full 128B row
        uint32_t dst = dbase + (uint32_t)(w * FA_KV_TILE + r * AST + c * 8) * 2;
        cp16(dst, gkv[w] + off + (long)r * DIN + c * 8);
    }
}

__global__ __launch_bounds__(256, 2) void flash_mma_kernel() {
    extern __shared__ __nv_bfloat16 sm[];
    const uint32_t sb = smem_u32(sm);
    const int t = threadIdx.x, warp = t >> 5, lane = t & 31;
    const int b = blockIdx.z, h = blockIdx.y;
    const int q0 = blockIdx.x * 128;

    __nv_bfloat16* sQh = sm;
    __nv_bfloat16* sQl = sm + FA_Q_UNITS;
    const uint32_t bQh = sb;
    const uint32_t bQl = sb + FA_Q_UNITS * 2;
    const uint32_t bKV = sb + 2 * FA_Q_UNITS * 2;

    const int a_r  = (lane & 7) + ((lane >> 3) & 1) * 8;
    const int a_kk = (lane >> 4) * 8;
    const int b_n  = (lane & 7) + (lane >> 4) * 8;
    const int b_kk = ((lane >> 3) & 1) * 8;
    const int v_kv = (lane & 7) + ((lane >> 3) & 1) * 8;
    const int v_d  = (lane >> 4) * 8;

    const long kvbase0 = (long)(b * SS) * DIN + h * DH;
    const __nv_bfloat16* gkv[4];
    gkv[0] = g_Kh + kvbase0; gkv[1] = g_Kl + kvbase0;
    gkv[2] = g_Vh + kvbase0; gkv[3] = g_Vl + kvbase0;

    issue_kv(bKV, gkv, 0, t);
    CP_COMMIT();

    {
        long base = (long)(b * SS + q0) * DIN + h * DH;
#pragma unroll
        for (int i = 0; i < 4; i++) {
            int u = t + 256 * i;
            int r = u >> 3, c = u & 7;
            *(uint4*)(sQh + r * AST + c * 8) = *(const uint4*)(g_Qh + base + (long)r * DIN + c * 8);
            *(uint4*)(sQl + r * AST + c * 8) = *(const uint4*)(g_Ql + base + (long)r * DIN + c * 8);
        }
    }

    float oacc[8][4];
#pragma unroll
    for (int i = 0; i < 8; i++)
#pragma unroll
        for (int j = 0; j < 4; j++) oacc[i][j] = 0.f;
    float m0 = -1e30f, m1 = -1e30f, sl0 = 0.f, sl1 = 0.f;

    const int NKB = SS / 64;
    for (int kb = 0; kb < NKB; kb++) {
        const int cur = kb & 1;
        CP_WAIT0();
        __syncthreads();
        if (kb + 1 < NKB) {
            issue_kv(bKV + (uint32_t)((1 - cur) * FA_STAGE_UNITS) * 2,
                     gkv, (long)(kb + 1) * 64 * DIN, t);
            CP_COMMIT();
        }

        const uint32_t bKh = bKV + (uint32_t)(cur * FA_STAGE_UNITS) * 2;
        const uint32_t bKl = bKh + FA_KV_TILE * 2;
        const uint32_t bVh = bKl + FA_KV_TILE * 2;
        const uint32_t bVl = bVh + FA_KV_TILE * 2;

        float sacc[8][4];
#pragma unroll
        for (int i = 0; i < 8; i++)
#pragma unroll
            for (int j = 0; j < 4; j++) sacc[i][j] = 0.f;

#pragma unroll
        for (int ks = 0; ks < 4; ks++) {
            uint32_t ah[4], al[4];
            uint32_t qoff = (uint32_t)((warp * 16 + a_r) * AST + ks * 16 + a_kk) * 2;
            ldsm4(ah, bQh + qoff);
            ldsm4(al, bQl + qoff);
#pragma unroll
            for (int g = 0; g < 4; g++) {
                uint32_t kh4[4], kl4[4];
                uint32_t koff = (uint32_t)((g * 16 + b_n) * AST + ks * 16 + b_kk) * 2;
                ldsm4(kh4, bKh + koff);
                ldsm4(kl4, bKl + koff);
                mma16816(sacc[g * 2],     ah, kh4);
                mma16816(sacc[g * 2],     ah, kl4);
                mma16816(sacc[g * 2],     al, kh4);
                mma16816(sacc[g * 2 + 1], ah, kh4 + 2);
                mma16816(sacc[g * 2 + 1], ah, kl4 + 2);
                mma16816(sacc[g * 2 + 1], al, kh4 + 2);
            }
        }

        float mx0 = -1e30f, mx1 = -1e30f;
#pragma unroll
        for (int nf = 0; nf < 8; nf++) {
            mx0 = fmaxf(mx0, fmaxf(sacc[nf][0], sacc[nf][1]));
            mx1 = fmaxf(mx1, fmaxf(sacc[nf][2], sacc[nf][3]));
        }
        mx0 = fmaxf(mx0, __shfl_xor_sync(0xffffffffu, mx0, 1));
        mx0 = fmaxf(mx0, __shfl_xor_sync(0xffffffffu, mx0, 2));
        mx1 = fmaxf(mx1, __shfl_xor_sync(0xffffffffu, mx1, 1));
        mx1 = fmaxf(mx1, __shfl_xor_sync(0xffffffffu, mx1, 2));

        float nm0 = fmaxf(m0, mx0), nm1 = fmaxf(m1, mx1);
        float al0 = exp2f(m0 - nm0), al1 = exp2f(m1 - nm1);
        float rs0 = 0.f, rs1 = 0.f;
#pragma unroll
        for (int nf = 0; nf < 8; nf++) {
            sacc[nf][0] = exp2f(sacc[nf][0] - nm0);
            sacc[nf][1] = exp2f(sacc[nf][1] - nm0);
            sacc[nf][2] = exp2f(sacc[nf][2] - nm1);
            sacc[nf][3] = exp2f(sacc[nf][3] - nm1);
            rs0 += sacc[nf][0] + sacc[nf][1];
            rs1 += sacc[nf][2] + sacc[nf][3];
        }
        rs0 += __shfl_xor_sync(0xffffffffu, rs0, 1);
        rs0 += __shfl_xor_sync(0xffffffffu, rs0, 2);
        rs1 += __shfl_xor_sync(0xffffffffu, rs1, 1);
        rs1 += __shfl_xor_sync(0xffffffffu, rs1, 2);
        sl0 = sl0 * al0 + rs0;  m0 = nm0;
        sl1 = sl1 * al1 + rs1;  m1 = nm1;
#pragma unroll
        for (int gd = 0; gd < 8; gd++) {
            oacc[gd][0] *= al0;  oacc[gd][1] *= al0;
            oacc[gd][2] *= al1;  oacc[gd][3] *= al1;
        }

        uint32_t ph[4][4], pl[4][4];
#pragma unroll
        for (int ks = 0; ks < 4; ks++) {
#pragma unroll
            for (int q = 0; q < 2; q++) {
                int nf = 2 * ks + q;
#pragma unroll
                for (int hf = 0; hf < 2; hf++) {
                    float p0 = sacc[nf][hf * 2 + 0];
                    float p1 = sacc[nf][hf * 2 + 1];
                    __nv_bfloat16 b0 = __float2bfloat16(p0);
                    __nv_bfloat16 b1 = __float2bfloat16(p1);
                    uint16_t b0u = *(uint16_t*)&b0, b1u = *(uint16_t*)&b1;
                    ph[ks][q * 2 + hf] = (uint32_t)b0u | ((uint32_t)b1u << 16);
                    pl[ks][q * 2 + hf] = packbf(p0 - __bfloat162float(b0),
                                                p1 - __bfloat162float(b1));
                }
            }
        }

#pragma unroll
        for (int ks = 0; ks < 4; ks++) {
#pragma unroll
            for (int g = 0; g < 4; g++) {
                uint32_t vh4[4], vl4[4];
                uint32_t voff = (uint32_t)((ks * 16 + v_kv) * AST + g * 16 + v_d) * 2;
                ldsm4t(vh4, bVh + voff);
                ldsm4t(vl4, bVl + voff);
                mma16816(oacc[g * 2],     ph[ks], vh4);
                mma16816(oacc[g * 2],     ph[ks], vl4);
                mma16816(oacc[g * 2],     pl[ks], vh4);
                mma16816(oacc[g * 2 + 1], ph[ks], vh4 + 2);
                mma16816(oacc[g * 2 + 1], ph[ks], vl4 + 2);
                mma16816(oacc[g * 2 + 1], pl[ks], vh4 + 2);
            }
        }
    }

    float inv0 = 1.f / sl0, inv1 = 1.f / sl1;
    long row0 = (long)(b * SS + q0 + warp * 16 + (lane >> 2));
    int colb = h * DH + (lane & 3) * 2;
#pragma unroll
    for (int gd = 0; gd < 8; gd++) {
        int col = colb + gd * 8;
        {
            float v0 = oacc[gd][0] * inv0, v1 = oacc[gd][1] * inv0;
            __nv_bfloat16 h0 = __float2bfloat16(v0), h1 = __float2bfloat16(v1);
            uint16_t h0u = *(uint16_t*)&h0, h1u = *(uint16_t*)&h1;
            *(uint32_t*)(g_Oh + row0 * DIN + col) = (uint32_t)h0u | ((uint32_t)h1u << 16);
            *(uint32_t*)(g_Ol + row0 * DIN + col) =
                packbf(v0 - __bfloat162float(h0), v1 - __bfloat162float(h1));
        }
        {
            float v0 = oacc[gd][2] * inv1, v1 = oacc[gd][3] * inv1;
            __nv_bfloat16 h0 = __float2bfloat16(v0), h1 = __float2bfloat16(v1);
            uint16_t h0u = *(uint16_t*)&h0, h1u = *(uint16_t*)&h1;
            *(uint32_t*)(g_Oh + (row0 + 8) * DIN + col) = (uint32_t)h0u | ((uint32_t)h1u << 16);
            *(uint32_t*)(g_Ol + (row0 + 8) * DIN + col) =
                packbf(v0 - __bfloat162float(h0), v1 - __bfloat162float(h1));
        }
    }
}

// ---------------- launcher ---------------------------------------------------
extern "C" void kernel_launch(void* const* d_in, const int* in_sizes, int n_in,
                              void* d_out, int out_size) {
    const float* query = (const float*)d_in[0];
    const float* key_  = (const float*)d_in[1];
    const float* value = (const float*)d_in[2];
    const float* Wq = (const float*)d_in[3];
    const float* bq = (const float*)d_in[4];
    const float* Wk = (const float*)d_in[5];
    const float* bk = (const float*)d_in[6];
    const float* Wv = (const float*)d_in[7];
    const float* bv = (const float*)d_in[8];
    const float* Wo = (const float*)d_in[9];
    const float* bo = (const float*)d_in[10];
    float* out = (float*)d_out;

    __nv_bfloat16 *pWh, *pWl, *pOh, *pOl;
    cudaGetSymbolAddress((void**)&pWh, g_Wh);
    cudaGetSymbolAddress((void**)&pWl, g_Wl);
    cudaGetSymbolAddress((void**)&pOh, g_Oh);
    cudaGetSymbolAddress((void**)&pOl, g_Ol);

    cudaFuncSetAttribute(gemm_qkv,
                         cudaFuncAttributeMaxDynamicSharedMemorySize, SMEM_GEMM);
    cudaFuncSetAttribute(gemm_out,
                         cudaFuncAttributeMaxDynamicSharedMemorySize, SMEM_GEMM);
    cudaFuncSetAttribute(flash_mma_kernel,
                         cudaFuncAttributeMaxDynamicSharedMemorySize, SMEM_FA);

    wsplit_kernel<<<dim3(DIN * DIN / 256, 4), 256>>>(Wq, Wk, Wv, Wo);

    gemm_qkv<<<dim3(DIN / 128, MROWS / 128, 3), 256, SMEM_GEMM>>>(
        query, key_, value, bq, bk, bv);

    flash_mma_kernel<<<dim3(SS / 128, HH, BB), 256, SMEM_FA>>>();

    gemm_out<<<dim3(DIN / 128, MROWS / 128), 256, SMEM_GEMM>>>(
        pOh, pOl, pWh + 3 * DIN * DIN, pWl + 3 * DIN * DIN, bo, out);
}